// round 12
// baseline (speedup 1.0000x reference)
#include <cuda_runtime.h>
#include <math.h>
#include <stdint.h>

// Problem constants (fixed shapes from setup_inputs)
#define B      1024
#define L      128
#define KPOS   8
#define NNEG   2048
#define NW     (B*KPOS + NNEG)   // 10240 W rows
#define NR     (B + NW)          // 11264 total rows
#define ROW_W0 B
#define ROW_N0 (B + B*KPOS)      // first negative row = 9216
#define EDIM   256
#define H      4
#define HD     64
#define P      16
#define M      32
#define R      2
#define NUML   131072

// Quadrature constants (double precision folded at compile time)
#define SQRT2_D 1.4142135623730951
#define CC      2.000001
__device__ __constant__ float c_s[2] = { (float)((2.0 - SQRT2_D)/CC), (float)((2.0 + SQRT2_D)/CC) };
__device__ __constant__ float c_w[2] = { (float)((2.0 + SQRT2_D)/(4.0*CC)), (float)((2.0 - SQRT2_D)/(4.0*CC)) };
#define INV_SQRT_M 0.17677669253f   // 1/sqrt(32.000001)

// Scratch (static device globals: allocation-free)
__device__ float d_anchT[HD*P];             // normalized anchors, transposed [d][p]
__device__ float d_omT  [HD*R*H*M];         // omega/8, transposed [d][r*128+h*32+m]
__device__ float d_x    [B*EDIM];           // pooled queries only
__device__ float d_poly [(size_t)NR*H*P];   // [row][h*16+p]
__device__ float d_prf  [(size_t)NR*R*H*M]; // [row][r*128+h*32+m]
__device__ float d_T    [R*H*P*M];          // [rh][p*32+m]
__device__ float    d_acc[2];               // {sum numer, sum label_mask}
__device__ unsigned d_cnt;

__device__ __forceinline__ float warpsum(float v) {
    #pragma unroll
    for (int o = 16; o; o >>= 1) v += __shfl_xor_sync(0xffffffffu, v, o);
    return v;
}

#define FFMA2(acc, x2, o2) \
    asm("fma.rn.f32x2 %0, %1, %2, %0;" : "+l"(acc) : "l"(x2), "l"(o2))
#define PACK2(o2, f) \
    asm("mov.b64 %0, {%1, %1};" : "=l"(o2) : "r"(__float_as_uint(f)))
#define UNPACK2(lo, hi, a) \
    asm("mov.b64 {%0, %1}, %2;" : "=r"(lo), "=r"(hi) : "l"(a))

// ---------------------------------------------------------------- prep: anchors + omega transpose + zero
__global__ void __launch_bounds__(256) prep_kernel(
        const float* __restrict__ anchors, const float* __restrict__ omega) {
    int bx = blockIdx.x, t = threadIdx.x;
    if (bx < 4) {                         // anchors: 4 p per block
        __shared__ float sred[8];
        int p = bx*4 + (t >> 6), d = t & 63;
        float v = anchors[p*HD + d];
        float s = warpsum(v*v);
        if ((t & 31) == 0) sred[t >> 5] = s;
        __syncthreads();
        int wp = (t >> 6)*2;
        d_anchT[d*P + p] = v / sqrtf(sred[wp] + sred[wp+1]);  // reference: no eps
    } else if (bx < 68) {                 // omega transpose (+ /sqrt(HD) fold)
        int e = (bx - 4)*256 + t;         // [r][h][d][m] linear
        int m = e & 31, d = (e >> 5) & 63, h = (e >> 11) & 3, r = e >> 13;
        d_omT[d*256 + r*128 + h*32 + m] = omega[e] * 0.125f;
    } else {                              // zero T + loss accumulators
        #pragma unroll
        for (int k = 0; k < 16; ++k) d_T[k*256 + t] = 0.f;
        if (t < 2) d_acc[t] = 0.f;
        if (t == 2) d_cnt = 0u;
    }
}

// ---------------------------------------------------------------- pool: 1 query/block, L split in half
__global__ void __launch_bounds__(256) pool_kernel(
        const int* __restrict__ indices, const float* __restrict__ mask,
        const float* __restrict__ embed) {
    __shared__ int    sidx[L];
    __shared__ float  smk [L];
    __shared__ float2 spart[128];
    __shared__ float  redm[4];
    int b = blockIdx.x, t = threadIdx.x;
    int c2 = t & 127, half = t >> 7;

    if (t < L) { sidx[t] = indices[b*L + t]; smk[t] = mask[b*L + t]; }
    __syncthreads();
    if (t < L) {
        float mv = warpsum(smk[t]);
        if ((t & 31) == 0) redm[t >> 5] = mv;
    }

    float2 acc = make_float2(0.f, 0.f);
    const float* ebase = embed + 2*c2;
    int l0 = half*64;
    #pragma unroll 8
    for (int i = 0; i < 64; ++i) {
        int l = l0 + i;
        float2 e = *(const float2*)(ebase + (size_t)sidx[l]*EDIM);
        float mk = smk[l];
        acc.x += e.x*mk; acc.y += e.y*mk;
    }
    if (half == 1) spart[c2] = acc;
    __syncthreads();
    if (half == 0) {
        float msum = redm[0]+redm[1]+redm[2]+redm[3];
        float inv = 1.f / fmaxf(msum, 1.0f);
        float2 o = spart[c2];
        *(float2*)(d_x + b*EDIM + 2*c2) =
            make_float2((acc.x + o.x)*inv, (acc.y + o.y)*inv);
    }
}

// ---------------------------------------------------------------- featurize 32 rows (v[] preloaded)
struct FeatSm {
    float xs[EDIM*36];
    float spart [32][8];
    float sscale[32][4];
    int   sj[32];
};

__device__ __forceinline__ void featurize(FeatSm& s, float v[32], int rowbase, int t) {
    int lane = t & 31, warp = t >> 5;
    #pragma unroll
    for (int g = 0; g < 32; ++g) {
        s.xs[t*36 + g] = v[g];
        float ss = warpsum(v[g]*v[g]);
        if (lane == 0) s.spart[g][warp] = ss;
    }
    __syncthreads();

    if (t < 128) {     // combined full-row + per-head scale, one reduction round
        int g = t >> 2, h = t & 3;
        float tot = s.spart[g][0]+s.spart[g][1]+s.spart[g][2]+s.spart[g][3]
                  + s.spart[g][4]+s.spart[g][5]+s.spart[g][6]+s.spart[g][7];
        float hn  = s.spart[g][2*h] + s.spart[g][2*h+1];
        float S1  = fmaxf(sqrtf(tot), 1e-4f);
        float S2  = fmaxf(sqrtf(hn)/S1, 1e-4f);
        s.sscale[g][h] = 1.0f / (S1*S2);
    }
    __syncthreads();

    // ---- prf: thread t -> feat col t = (r,h,m); omega in registers ----
    {
        float om[64];
        const float* omp = d_omT + t;
        #pragma unroll
        for (int d = 0; d < 64; ++d) om[d] = omp[d*256];
        int h = (t >> 5) & 3, r = t >> 7;
        const float* xsh = s.xs + h*64*36;
        float qs = c_s[r];
        float sc = sqrtf(2.f*qs);
        float ml = sqrtf(c_w[r]) * INV_SQRT_M;
        float* outp = d_prf + (size_t)rowbase*256 + t;
        #pragma unroll
        for (int tile = 0; tile < 4; ++tile) {
            unsigned long long a0=0, a1=0, a2=0, a3=0;
            #pragma unroll
            for (int d = 0; d < 64; ++d) {
                unsigned long long o2; PACK2(o2, om[d]);
                const ulonglong2* xp = (const ulonglong2*)(xsh + d*36 + tile*8);
                ulonglong2 xa = xp[0], xb = xp[1];
                FFMA2(a0, xa.x, o2); FFMA2(a1, xa.y, o2);
                FFMA2(a2, xb.x, o2); FFMA2(a3, xb.y, o2);
            }
            unsigned long long aa[4] = {a0, a1, a2, a3};
            #pragma unroll
            for (int pr = 0; pr < 4; ++pr) {
                unsigned lo, hi; UNPACK2(lo, hi, aa[pr]);
                int g0 = tile*8 + pr*2;
                float f0 = __uint_as_float(lo) * s.sscale[g0  ][h];
                float f1 = __uint_as_float(hi) * s.sscale[g0+1][h];
                outp[(size_t)(g0  )*256] = __expf(fminf(fmaxf(f0*sc - qs, -20.f), 20.f)) * ml;
                outp[(size_t)(g0+1)*256] = __expf(fminf(fmaxf(f1*sc - qs, -20.f), 20.f)) * ml;
            }
        }
    }

    // ---- poly: thread t -> (p, hh) x 8 rows; anchors in registers ----
    {
        int p = t & 15, hh = (t >> 4) & 3, slot = t >> 6;
        float an[64];
        #pragma unroll
        for (int d = 0; d < 64; ++d) an[d] = d_anchT[d*P + p];
        const float* xph = s.xs + hh*64*36 + slot*8;
        unsigned long long a0=0, a1=0, a2=0, a3=0;
        #pragma unroll
        for (int d = 0; d < 64; ++d) {
            unsigned long long o2; PACK2(o2, an[d]);
            const ulonglong2* xp = (const ulonglong2*)(xph + d*36);
            ulonglong2 xa = xp[0], xb = xp[1];
            FFMA2(a0, xa.x, o2); FFMA2(a1, xa.y, o2);
            FFMA2(a2, xb.x, o2); FFMA2(a3, xb.y, o2);
        }
        unsigned long long aa[4] = {a0, a1, a2, a3};
        #pragma unroll
        for (int pr = 0; pr < 4; ++pr) {
            unsigned lo, hi; UNPACK2(lo, hi, aa[pr]);
            int g0 = slot*8 + pr*2;
            float f0 = __uint_as_float(lo) * s.sscale[g0  ][hh];
            float f1 = __uint_as_float(hi) * s.sscale[g0+1][hh];
            f0 = fminf(fmaxf(f0, -1.f), 1.f);
            f1 = fminf(fmaxf(f1, -1.f), 1.f);
            d_poly[(size_t)(rowbase + g0  )*64 + hh*16 + p] = f0*f0*0.25f;
            d_poly[(size_t)(rowbase + g0+1)*64 + hh*16 + p] = f1*f1*0.25f;
        }
    }
}

// ---------------------------------------------------------------- featW: gather + featurize (stream 2)
__global__ void __launch_bounds__(256, 2) featW_kernel(
        const int* __restrict__ labels, const int* __restrict__ negidx,
        const float* __restrict__ kernelM) {
    __shared__ FeatSm sm;
    int t = threadIdx.x;
    int base = ROW_W0 + blockIdx.x * 32;
    if (t < 32) {
        int i = base + t - B;
        sm.sj[t] = (i < B*KPOS) ? max(__ldg(labels + i), 0) : __ldg(negidx + i - B*KPOS);
    }
    __syncthreads();
    float v[32];
    #pragma unroll
    for (int g = 0; g < 32; ++g) v[g] = __ldg(kernelM + (size_t)t*NUML + sm.sj[g]);
    featurize(sm, v, base, t);
}

// ---------------------------------------------------------------- featQ (stream 0, after pool)
__global__ void __launch_bounds__(256, 2) featQ_kernel() {
    __shared__ FeatSm sm;
    int t = threadIdx.x;
    int base = blockIdx.x * 32;
    float v[32];
    #pragma unroll
    for (int g = 0; g < 32; ++g) v[g] = d_x[(base + g)*EDIM + t];
    featurize(sm, v, base, t);
}

// ---------------------------------------------------------------- T = sum over neg rows of polyW (x) prfW
__global__ void t_kernel() {
    int rh = blockIdx.x & 7, chunk = blockIdx.x >> 3;   // 16 chunks x 8 rh
    int r = rh >> 2, h = rh & 3;
    int t = threadIdx.x;                 // 512 threads
    int p = t >> 5, m = t & 31;
    __shared__ float spw[32][16];
    __shared__ float spf[32][32];
    float acc = 0.f;
    for (int iter = 0; iter < 4; ++iter) {
        int bs = ROW_N0 + chunk*128 + iter*32;
        int lr = t >> 4, lp = t & 15;
        spw[lr][lp] = d_poly[(size_t)(bs + lr)*64 + h*16 + lp];
        int fr = t >> 5, fm = t & 31;
        spf[fr     ][fm] = d_prf[(size_t)(bs+fr   )*256 + r*128 + h*32 + fm];
        spf[fr + 16][fm] = d_prf[(size_t)(bs+fr+16)*256 + r*128 + h*32 + fm];
        __syncthreads();
        #pragma unroll
        for (int k = 0; k < 32; ++k) acc += spw[k][p]*spf[k][m];
        __syncthreads();
    }
    atomicAdd(&d_T[rh*512 + t], acc);
}

// ---------------------------------------------------------------- per-row loss (1 b/block) + fused final
__global__ void __launch_bounds__(256) rowloss_kernel(
        const float* __restrict__ label_mask, float* __restrict__ out) {
    __shared__ float spos[8];
    __shared__ float red[8];
    int b = blockIdx.x, t = threadIdx.x, lane = t & 31, warp = t >> 5;

    // --- positive score, warp w -> k=w: segmented 3-step + one full reduction ---
    size_t g = (size_t)(ROW_W0 + b*KPOS + warp);
    float2 pq = *(const float2*)(d_poly + (size_t)b*64 + lane*2);
    float2 pw = *(const float2*)(d_poly + g*64 + lane*2);
    float prod = pq.x*pw.x + pq.y*pw.y;           // partial polydot for h = lane>>3
    #pragma unroll
    for (int o = 4; o; o >>= 1) prod += __shfl_xor_sync(0xffffffffu, prod, o);
    float pdh[4];
    pdh[0] = __shfl_sync(0xffffffffu, prod, 0);
    pdh[1] = __shfl_sync(0xffffffffu, prod, 8);
    pdh[2] = __shfl_sync(0xffffffffu, prod, 16);
    pdh[3] = __shfl_sync(0xffffffffu, prod, 24);
    float val = 0.f;
    #pragma unroll
    for (int r = 0; r < R; ++r)
        #pragma unroll
        for (int h = 0; h < H; ++h)
            val += pdh[h] * d_prf[(size_t)b*256 + r*128 + h*32 + lane]
                          * d_prf[g*256 + r*128 + h*32 + lane];
    float score = warpsum(val);
    if (lane == 0) spos[warp] = score;

    // --- negative row-sum via T: thread t -> (r,h,m) ---
    int r = t >> 7, h = (t >> 5) & 3, m = t & 31;
    const float* Tp = d_T + (r*4 + h)*512 + m;
    float a = 0.f;
    #pragma unroll
    for (int p = 0; p < P; ++p) a += d_poly[(size_t)b*64 + h*16 + p] * Tp[p*32];
    float nval = warpsum(d_prf[(size_t)b*256 + t] * a);
    if (lane == 0) red[warp] = nval;
    __syncthreads();

    if (t == 0) {
        float S = (float)NNEG * 1e-8f;
        #pragma unroll
        for (int w = 0; w < 8; ++w) S += red[w];
        #pragma unroll
        for (int k = 0; k < KPOS; ++k) S += spos[k] + 1e-8f;
        float logS = logf(S);
        float lg = 0.f, lm = 0.f;
        #pragma unroll
        for (int k = 0; k < KPOS; ++k) {
            float mk = label_mask[b*KPOS + k];
            lg += mk * (logf(spos[k] + 1e-8f) - logS);
            lm += mk;
        }
        atomicAdd(&d_acc[0], lg);
        atomicAdd(&d_acc[1], lm);
        __threadfence();
        if (atomicAdd(&d_cnt, 1u) == (unsigned)(B - 1)) {
            __threadfence();
            out[0] = -d_acc[0] / (d_acc[1] + 1e-6f);
        }
    }
}

// ---------------------------------------------------------------- launch (round-8 fork-join shape)
static cudaStream_t g_s2 = 0;
static cudaEvent_t  g_ev0 = 0, g_ev2 = 0;

extern "C" void kernel_launch(void* const* d_in, const int* in_sizes, int n_in,
                              void* d_out, int out_size) {
    const int*   indices    = (const int*)  d_in[0];
    const float* mask       = (const float*)d_in[1];
    const int*   labels     = (const int*)  d_in[2];
    const float* label_mask = (const float*)d_in[3];
    const int*   neg_idx    = (const int*)  d_in[4];
    const float* embed      = (const float*)d_in[5];
    const float* kernelM    = (const float*)d_in[6];
    const float* omega      = (const float*)d_in[7];
    const float* anchors    = (const float*)d_in[8];
    float* out = (float*)d_out;

    if (!g_s2) {   // host-side objects only; identical device work every call
        cudaStreamCreateWithFlags(&g_s2, cudaStreamNonBlocking);
        cudaEventCreateWithFlags(&g_ev0, cudaEventDisableTiming);
        cudaEventCreateWithFlags(&g_ev2, cudaEventDisableTiming);
    }

    // stream 0: prep first (capture stream), then fork
    prep_kernel<<<69, 256>>>(anchors, omega);
    cudaEventRecord(g_ev0, 0);
    cudaStreamWaitEvent(g_s2, g_ev0, 0);

    // stream 2: W-feature pipeline
    featW_kernel<<<NW/32, 256, 0, g_s2>>>(labels, neg_idx, kernelM);
    t_kernel    <<<128,   512, 0, g_s2>>>();
    cudaEventRecord(g_ev2, g_s2);

    // stream 0: query pipeline
    pool_kernel <<<B,    256>>>(indices, mask, embed);
    featQ_kernel<<<B/32, 256>>>();

    cudaStreamWaitEvent(0, g_ev2, 0);
    rowloss_kernel<<<B, 256>>>(label_mask, out);
}

// round 13
// speedup vs baseline: 1.0362x; 1.0362x over previous
#include <cuda_runtime.h>
#include <math.h>
#include <stdint.h>

// Problem constants (fixed shapes from setup_inputs)
#define B      1024
#define L      128
#define KPOS   8
#define NNEG   2048
#define NW     (B*KPOS + NNEG)   // 10240 W rows
#define NR     (B + NW)          // 11264 total rows
#define ROW_W0 B
#define ROW_N0 (B + B*KPOS)      // first negative row = 9216
#define EDIM   256
#define H      4
#define HD     64
#define P      16
#define M      32
#define R      2
#define NUML   131072

// Quadrature constants (double precision folded at compile time)
#define SQRT2_D 1.4142135623730951
#define CC      2.000001
__device__ __constant__ float c_s[2] = { (float)((2.0 - SQRT2_D)/CC), (float)((2.0 + SQRT2_D)/CC) };
__device__ __constant__ float c_w[2] = { (float)((2.0 + SQRT2_D)/(4.0*CC)), (float)((2.0 - SQRT2_D)/(4.0*CC)) };
#define INV_SQRT_M 0.17677669253f   // 1/sqrt(32.000001)

// Scratch (static device globals: allocation-free)
__device__ float d_anchT[HD*P];             // normalized anchors, transposed [d][p]
__device__ float d_omT  [HD*R*H*M];         // omega/8, transposed [d][r*128+h*32+m]
__device__ float d_x    [B*EDIM];           // pooled queries only
__device__ float d_poly [(size_t)NR*H*P];   // [row][h*16+p]
__device__ float d_prf  [(size_t)NR*R*H*M]; // [row][r*128+h*32+m]
__device__ float d_T    [R*H*P*M];          // [rh][p*32+m]
__device__ float d_pos  [B*KPOS];
__device__ float    d_acc[2];               // {sum numer, sum label_mask}
__device__ unsigned d_cnt;

__device__ __forceinline__ float warpsum(float v) {
    #pragma unroll
    for (int o = 16; o; o >>= 1) v += __shfl_xor_sync(0xffffffffu, v, o);
    return v;
}

#define FFMA2(acc, x2, o2) \
    asm("fma.rn.f32x2 %0, %1, %2, %0;" : "+l"(acc) : "l"(x2), "l"(o2))
#define PACK2(o2, f) \
    asm("mov.b64 %0, {%1, %1};" : "=l"(o2) : "r"(__float_as_uint(f)))
#define UNPACK2(lo, hi, a) \
    asm("mov.b64 {%0, %1}, %2;" : "=r"(lo), "=r"(hi) : "l"(a))

// ---------------------------------------------------------------- prep: anchors + omega transpose + zero
__global__ void __launch_bounds__(256) prep_kernel(
        const float* __restrict__ anchors, const float* __restrict__ omega) {
    int bx = blockIdx.x, t = threadIdx.x;
    if (bx < 4) {                         // anchors: 4 p per block
        __shared__ float sred[8];
        int p = bx*4 + (t >> 6), d = t & 63;
        float v = anchors[p*HD + d];
        float s = warpsum(v*v);
        if ((t & 31) == 0) sred[t >> 5] = s;
        __syncthreads();
        int wp = (t >> 6)*2;
        d_anchT[d*P + p] = v / sqrtf(sred[wp] + sred[wp+1]);  // reference: no eps
    } else if (bx < 68) {                 // omega transpose (+ /sqrt(HD) fold)
        int e = (bx - 4)*256 + t;         // [r][h][d][m] linear
        int m = e & 31, d = (e >> 5) & 63, h = (e >> 11) & 3, r = e >> 13;
        d_omT[d*256 + r*128 + h*32 + m] = omega[e] * 0.125f;
    } else {                              // zero T + loss accumulators
        #pragma unroll
        for (int k = 0; k < 16; ++k) d_T[k*256 + t] = 0.f;
        if (t < 2) d_acc[t] = 0.f;
        if (t == 2) d_cnt = 0u;
    }
}

// ---------------------------------------------------------------- pool: 2 queries/block (round-8 proven)
__global__ void __launch_bounds__(256) pool_kernel(
        const int* __restrict__ indices, const float* __restrict__ mask,
        const float* __restrict__ embed) {
    __shared__ int   sidx[2][L];
    __shared__ float smk [2][L];
    __shared__ float redm[2][4];
    int bx = blockIdx.x, t = threadIdx.x;
    int q = t >> 7, c = t & 127;
    int b = bx*2 + q;
    sidx[q][c] = indices[b*L + c];
    smk [q][c] = mask   [b*L + c];
    __syncthreads();
    float mv = warpsum(smk[q][c]);
    if ((t & 31) == 0) redm[q][(t >> 5) & 3] = mv;
    __syncthreads();
    float msum = redm[q][0]+redm[q][1]+redm[q][2]+redm[q][3];
    float2 acc = make_float2(0.f, 0.f);
    const float* ebase = embed + 2*c;
    #pragma unroll 8
    for (int l = 0; l < L; ++l) {
        float2 e = *(const float2*)(ebase + (size_t)sidx[q][l]*EDIM);
        float mk = smk[q][l];
        acc.x += e.x*mk; acc.y += e.y*mk;
    }
    float inv = 1.f / fmaxf(msum, 1.0f);
    *(float2*)(d_x + b*EDIM + 2*c) = make_float2(acc.x*inv, acc.y*inv);
}

// ---------------------------------------------------------------- featurize 32 rows (v[] preloaded)
// DIRECT=true: read omega/anchors straight from inputs (no prep dependency).
struct FeatSm {
    float xs[EDIM*36];
    float spart [32][8];
    float sscale[32][4];
    int   sj[32];
};

template<bool DIRECT>
__device__ __forceinline__ void featurize(FeatSm& s,
                                          const float* __restrict__ omega,
                                          const float* __restrict__ anchors,
                                          float v[32], int rowbase, int t) {
    int lane = t & 31, warp = t >> 5;
    #pragma unroll
    for (int g = 0; g < 32; ++g) {
        s.xs[t*36 + g] = v[g];
        float ss = warpsum(v[g]*v[g]);
        if (lane == 0) s.spart[g][warp] = ss;
    }
    __syncthreads();

    if (t < 128) {     // combined full-row + per-head scale, one reduction round
        int g = t >> 2, h = t & 3;
        float tot = s.spart[g][0]+s.spart[g][1]+s.spart[g][2]+s.spart[g][3]
                  + s.spart[g][4]+s.spart[g][5]+s.spart[g][6]+s.spart[g][7];
        float hn  = s.spart[g][2*h] + s.spart[g][2*h+1];
        float S1  = fmaxf(sqrtf(tot), 1e-4f);
        float S2  = fmaxf(sqrtf(hn)/S1, 1e-4f);
        s.sscale[g][h] = 1.0f / (S1*S2);
    }
    __syncthreads();

    // ---- prf: thread t -> feat col t = (r,h,m); omega in registers ----
    {
        int h = (t >> 5) & 3, r = t >> 7;
        float om[64];
        if (DIRECT) {
            const float* omp = omega + ((r*H + h)*HD)*M + (t & 31);
            #pragma unroll
            for (int d = 0; d < 64; ++d) om[d] = __ldg(omp + d*M);
        } else {
            const float* omp = d_omT + t;
            #pragma unroll
            for (int d = 0; d < 64; ++d) om[d] = omp[d*256];
        }
        const float* xsh = s.xs + h*64*36;
        float qs = c_s[r];
        float sc = sqrtf(2.f*qs) * (DIRECT ? 0.125f : 1.0f);  // fold omega/sqrt(HD)
        float ml = sqrtf(c_w[r]) * INV_SQRT_M;
        float* outp = d_prf + (size_t)rowbase*256 + t;
        #pragma unroll
        for (int tile = 0; tile < 4; ++tile) {
            unsigned long long a0=0, a1=0, a2=0, a3=0;
            #pragma unroll
            for (int d = 0; d < 64; ++d) {
                unsigned long long o2; PACK2(o2, om[d]);
                const ulonglong2* xp = (const ulonglong2*)(xsh + d*36 + tile*8);
                ulonglong2 xa = xp[0], xb = xp[1];
                FFMA2(a0, xa.x, o2); FFMA2(a1, xa.y, o2);
                FFMA2(a2, xb.x, o2); FFMA2(a3, xb.y, o2);
            }
            unsigned long long aa[4] = {a0, a1, a2, a3};
            #pragma unroll
            for (int pr = 0; pr < 4; ++pr) {
                unsigned lo, hi; UNPACK2(lo, hi, aa[pr]);
                int g0 = tile*8 + pr*2;
                float f0 = __uint_as_float(lo) * s.sscale[g0  ][h];
                float f1 = __uint_as_float(hi) * s.sscale[g0+1][h];
                outp[(size_t)(g0  )*256] = __expf(fminf(fmaxf(f0*sc - qs, -20.f), 20.f)) * ml;
                outp[(size_t)(g0+1)*256] = __expf(fminf(fmaxf(f1*sc - qs, -20.f), 20.f)) * ml;
            }
        }
    }

    // ---- poly: thread t -> (p, hh) x 8 rows; anchors in registers ----
    {
        int p = t & 15, hh = (t >> 4) & 3, slot = t >> 6;
        float an[64];
        float invn = 1.0f;
        if (DIRECT) {
            float n2 = 0.f;
            #pragma unroll
            for (int d = 0; d < 64; ++d) { an[d] = __ldg(anchors + p*HD + d); n2 += an[d]*an[d]; }
            invn = 1.0f / sqrtf(n2);      // reference: no eps
        } else {
            #pragma unroll
            for (int d = 0; d < 64; ++d) an[d] = d_anchT[d*P + p];
        }
        const float* xph = s.xs + hh*64*36 + slot*8;
        unsigned long long a0=0, a1=0, a2=0, a3=0;
        #pragma unroll
        for (int d = 0; d < 64; ++d) {
            unsigned long long o2; PACK2(o2, an[d]);
            const ulonglong2* xp = (const ulonglong2*)(xph + d*36);
            ulonglong2 xa = xp[0], xb = xp[1];
            FFMA2(a0, xa.x, o2); FFMA2(a1, xa.y, o2);
            FFMA2(a2, xb.x, o2); FFMA2(a3, xb.y, o2);
        }
        unsigned long long aa[4] = {a0, a1, a2, a3};
        #pragma unroll
        for (int pr = 0; pr < 4; ++pr) {
            unsigned lo, hi; UNPACK2(lo, hi, aa[pr]);
            int g0 = slot*8 + pr*2;
            float f0 = __uint_as_float(lo) * s.sscale[g0  ][hh];
            float f1 = __uint_as_float(hi) * s.sscale[g0+1][hh];
            if (DIRECT) { f0 *= invn; f1 *= invn; }
            f0 = fminf(fmaxf(f0, -1.f), 1.f);
            f1 = fminf(fmaxf(f1, -1.f), 1.f);
            d_poly[(size_t)(rowbase + g0  )*64 + hh*16 + p] = f0*f0*0.25f;
            d_poly[(size_t)(rowbase + g0+1)*64 + hh*16 + p] = f1*f1*0.25f;
        }
    }
}

// ---------------------------------------------------------------- featW: gather + featurize (stream 2, NO prep dep)
__global__ void __launch_bounds__(256, 2) featW_kernel(
        const int* __restrict__ labels, const int* __restrict__ negidx,
        const float* __restrict__ kernelM,
        const float* __restrict__ omega, const float* __restrict__ anchors) {
    __shared__ FeatSm sm;
    int t = threadIdx.x;
    int base = ROW_W0 + blockIdx.x * 32;
    if (t < 32) {
        int i = base + t - B;
        sm.sj[t] = (i < B*KPOS) ? max(__ldg(labels + i), 0) : __ldg(negidx + i - B*KPOS);
    }
    __syncthreads();
    float v[32];
    #pragma unroll
    for (int g = 0; g < 32; ++g) v[g] = __ldg(kernelM + (size_t)t*NUML + sm.sj[g]);
    featurize<true>(sm, omega, anchors, v, base, t);
}

// ---------------------------------------------------------------- featQ (stream 0, after pool + prep)
__global__ void __launch_bounds__(256, 2) featQ_kernel() {
    __shared__ FeatSm sm;
    int t = threadIdx.x;
    int base = blockIdx.x * 32;
    float v[32];
    #pragma unroll
    for (int g = 0; g < 32; ++g) v[g] = d_x[(base + g)*EDIM + t];
    featurize<false>(sm, nullptr, nullptr, v, base, t);
}

// ---------------------------------------------------------------- T = sum over neg rows of polyW (x) prfW
__global__ void t_kernel() {
    int rh = blockIdx.x & 7, chunk = blockIdx.x >> 3;   // 16 chunks x 8 rh
    int r = rh >> 2, h = rh & 3;
    int t = threadIdx.x;                 // 512 threads
    int p = t >> 5, m = t & 31;
    __shared__ float spw[32][16];
    __shared__ float spf[32][32];
    float acc = 0.f;
    for (int iter = 0; iter < 4; ++iter) {
        int bs = ROW_N0 + chunk*128 + iter*32;
        int lr = t >> 4, lp = t & 15;
        spw[lr][lp] = d_poly[(size_t)(bs + lr)*64 + h*16 + lp];
        int fr = t >> 5, fm = t & 31;
        spf[fr     ][fm] = d_prf[(size_t)(bs+fr   )*256 + r*128 + h*32 + fm];
        spf[fr + 16][fm] = d_prf[(size_t)(bs+fr+16)*256 + r*128 + h*32 + fm];
        __syncthreads();
        #pragma unroll
        for (int k = 0; k < 32; ++k) acc += spw[k][p]*spf[k][m];
        __syncthreads();
    }
    atomicAdd(&d_T[rh*512 + t], acc);
}

// ---------------------------------------------------------------- per-row loss (2 b per block) + final
__global__ void rowloss_kernel(const float* __restrict__ label_mask,
                               float* __restrict__ out) {
    __shared__ float spos[2][8];
    __shared__ float red [2][8];
    int t = threadIdx.x, lane = t & 31, warp = t >> 5;
    int b0 = blockIdx.x*2;

    // --- positive scores: warp handles b = b0+(warp>>2), k = (warp&3)*2 + {0,1} ---
    {
        int b = b0 + (warp >> 2);
        float2 pq = *(const float2*)(d_poly + (size_t)b*64 + lane*2);
        float score[2];
        #pragma unroll
        for (int kk = 0; kk < 2; ++kk) {
            int k = (warp & 3)*2 + kk;
            size_t g = (size_t)(ROW_W0 + b*KPOS + k);
            float2 pw = *(const float2*)(d_poly + g*64 + lane*2);
            float prod = pq.x*pw.x + pq.y*pw.y;       // partial polydot for h = lane>>3
            #pragma unroll
            for (int o = 4; o; o >>= 1) prod += __shfl_xor_sync(0xffffffffu, prod, o);
            float pdh[4];
            pdh[0] = __shfl_sync(0xffffffffu, prod, 0);
            pdh[1] = __shfl_sync(0xffffffffu, prod, 8);
            pdh[2] = __shfl_sync(0xffffffffu, prod, 16);
            pdh[3] = __shfl_sync(0xffffffffu, prod, 24);
            float val = 0.f;
            #pragma unroll
            for (int r = 0; r < R; ++r)
                #pragma unroll
                for (int h = 0; h < H; ++h)
                    val += pdh[h] * d_prf[(size_t)b*256 + r*128 + h*32 + lane]
                                  * d_prf[g*256 + r*128 + h*32 + lane];
            score[kk] = warpsum(val);
        }
        if (lane == 0) {
            spos[warp >> 2][(warp & 3)*2    ] = score[0];
            spos[warp >> 2][(warp & 3)*2 + 1] = score[1];
        }
    }

    // --- negative row-sums via T for both b's: thread t -> (r,h,m) ---
    {
        int r = t >> 7, h = (t >> 5) & 3, m = t & 31;
        const float* Tp = d_T + (r*4 + h)*512 + m;
        #pragma unroll
        for (int bb = 0; bb < 2; ++bb) {
            int b = b0 + bb;
            float a = 0.f;
            #pragma unroll
            for (int p = 0; p < P; ++p) a += d_poly[(size_t)b*64 + h*16 + p] * Tp[p*32];
            float nval = warpsum(d_prf[(size_t)b*256 + t] * a);
            if (lane == 0) red[bb][warp] = nval;
        }
    }
    __syncthreads();

    // --- epilogue: warp0 lane0 -> b0, warp1 lane0 -> b0+1 ---
    if (lane == 0 && warp < 2) {
        int bb = warp, b = b0 + bb;
        float S = (float)NNEG * 1e-8f;
        #pragma unroll
        for (int w = 0; w < 8; ++w) S += red[bb][w];
        #pragma unroll
        for (int k = 0; k < KPOS; ++k) S += spos[bb][k] + 1e-8f;
        float logS = logf(S);
        float lg = 0.f, lm = 0.f;
        #pragma unroll
        for (int k = 0; k < KPOS; ++k) {
            float mk = label_mask[b*KPOS + k];
            lg += mk * (logf(spos[bb][k] + 1e-8f) - logS);
            lm += mk;
        }
        atomicAdd(&d_acc[0], lg);
        atomicAdd(&d_acc[1], lm);
        __threadfence();
        if (atomicAdd(&d_cnt, 1u) == (unsigned)(B - 1)) {
            __threadfence();
            out[0] = -d_acc[0] / (d_acc[1] + 1e-6f);
        }
    }
}

// ---------------------------------------------------------------- launch (featW starts at t=0)
static cudaStream_t g_s2 = 0;
static cudaEvent_t  g_evF = 0, g_evP = 0, g_ev2 = 0;

extern "C" void kernel_launch(void* const* d_in, const int* in_sizes, int n_in,
                              void* d_out, int out_size) {
    const int*   indices    = (const int*)  d_in[0];
    const float* mask       = (const float*)d_in[1];
    const int*   labels     = (const int*)  d_in[2];
    const float* label_mask = (const float*)d_in[3];
    const int*   neg_idx    = (const int*)  d_in[4];
    const float* embed      = (const float*)d_in[5];
    const float* kernelM    = (const float*)d_in[6];
    const float* omega      = (const float*)d_in[7];
    const float* anchors    = (const float*)d_in[8];
    float* out = (float*)d_out;

    if (!g_s2) {   // host-side objects only; identical device work every call
        cudaStreamCreateWithFlags(&g_s2, cudaStreamNonBlocking);
        cudaEventCreateWithFlags(&g_evF, cudaEventDisableTiming);
        cudaEventCreateWithFlags(&g_evP, cudaEventDisableTiming);
        cudaEventCreateWithFlags(&g_ev2, cudaEventDisableTiming);
    }

    // FORK from the capture stream before touching s2.
    cudaEventRecord(g_evF, 0);
    cudaStreamWaitEvent(g_s2, g_evF, 0);

    // s2: featW immediately (no prep dependency — reads omega/anchors directly)
    featW_kernel<<<NW/32, 256, 0, g_s2>>>(labels, neg_idx, kernelM, omega, anchors);

    // s0: pool immediately; prep after (featQ needs d_omT/d_anchT; t/rowloss need zeros)
    pool_kernel<<<B/2, 256>>>(indices, mask, embed);
    prep_kernel<<<69,  256>>>(anchors, omega);
    cudaEventRecord(g_evP, 0);

    // s2: t needs featW (stream order) AND prep's d_T zero (evP)
    cudaStreamWaitEvent(g_s2, g_evP, 0);
    t_kernel<<<128, 512, 0, g_s2>>>();
    cudaEventRecord(g_ev2, g_s2);

    // s0: featQ (after pool+prep), then join and finish
    featQ_kernel<<<B/32, 256>>>();
    cudaStreamWaitEvent(0, g_ev2, 0);
    rowloss_kernel<<<B/2, 256>>>(label_mask, out);
}

// round 14
// speedup vs baseline: 1.2652x; 1.2210x over previous
#include <cuda_runtime.h>
#include <math.h>
#include <stdint.h>

// Problem constants (fixed shapes from setup_inputs)
#define B      1024
#define L      128
#define KPOS   8
#define NNEG   2048
#define NW     (B*KPOS + NNEG)   // 10240 W rows
#define NR     (B + NW)          // 11264 total rows
#define ROW_W0 B
#define ROW_N0 (B + B*KPOS)      // first negative row = 9216
#define EDIM   256
#define H      4
#define HD     64
#define P      16
#define M      32
#define R      2
#define NUML   131072

// Quadrature constants (double precision folded at compile time)
#define SQRT2_D 1.4142135623730951
#define CC      2.000001
__device__ __constant__ float c_s[2] = { (float)((2.0 - SQRT2_D)/CC), (float)((2.0 + SQRT2_D)/CC) };
__device__ __constant__ float c_w[2] = { (float)((2.0 + SQRT2_D)/(4.0*CC)), (float)((2.0 - SQRT2_D)/(4.0*CC)) };
#define INV_SQRT_M 0.17677669253f   // 1/sqrt(32.000001)

// Scratch (static device globals: allocation-free)
__device__ float d_anchT[HD*P];             // normalized anchors, transposed [d][p]
__device__ float d_omT  [HD*R*H*M];         // omega/8, transposed [d][r*128+h*32+m]
__device__ float d_x    [B*EDIM];           // pooled queries only
__device__ float d_poly [(size_t)NR*H*P];   // [row][h*16+p]
__device__ float d_prf  [(size_t)NR*R*H*M]; // [row][r*128+h*32+m]
__device__ float d_T    [R*H*P*M];          // [rh][p*32+m]
__device__ float    d_acc[2];               // {sum numer, sum label_mask}
__device__ unsigned d_cnt;

__device__ __forceinline__ float warpsum(float v) {
    #pragma unroll
    for (int o = 16; o; o >>= 1) v += __shfl_xor_sync(0xffffffffu, v, o);
    return v;
}

#define FFMA2(acc, x2, o2) \
    asm("fma.rn.f32x2 %0, %1, %2, %0;" : "+l"(acc) : "l"(x2), "l"(o2))
#define PACK2(o2, f) \
    asm("mov.b64 %0, {%1, %1};" : "=l"(o2) : "r"(__float_as_uint(f)))
#define UNPACK2(lo, hi, a) \
    asm("mov.b64 {%0, %1}, %2;" : "=r"(lo), "=r"(hi) : "l"(a))

// ---------------------------------------------------------------- prep: anchors + omega transpose + zero
__global__ void __launch_bounds__(256) prep_kernel(
        const float* __restrict__ anchors, const float* __restrict__ omega) {
    int bx = blockIdx.x, t = threadIdx.x;
    if (bx < 4) {                         // anchors: 4 p per block
        __shared__ float sred[8];
        int p = bx*4 + (t >> 6), d = t & 63;
        float v = anchors[p*HD + d];
        float s = warpsum(v*v);
        if ((t & 31) == 0) sred[t >> 5] = s;
        __syncthreads();
        int wp = (t >> 6)*2;
        d_anchT[d*P + p] = v / sqrtf(sred[wp] + sred[wp+1]);  // reference: no eps
    } else if (bx < 68) {                 // omega transpose (+ /sqrt(HD) fold)
        int e = (bx - 4)*256 + t;         // [r][h][d][m] linear
        int m = e & 31, d = (e >> 5) & 63, h = (e >> 11) & 3, r = e >> 13;
        d_omT[d*256 + r*128 + h*32 + m] = omega[e] * 0.125f;
    } else {                              // zero T + loss accumulators
        #pragma unroll
        for (int k = 0; k < 16; ++k) d_T[k*256 + t] = 0.f;
        if (t < 2) d_acc[t] = 0.f;
        if (t == 2) d_cnt = 0u;
    }
}

// ---------------------------------------------------------------- pool: 2 queries/block (round-8 proven)
__global__ void __launch_bounds__(256) pool_kernel(
        const int* __restrict__ indices, const float* __restrict__ mask,
        const float* __restrict__ embed) {
    __shared__ int   sidx[2][L];
    __shared__ float smk [2][L];
    __shared__ float redm[2][4];
    int bx = blockIdx.x, t = threadIdx.x;
    int q = t >> 7, c = t & 127;
    int b = bx*2 + q;
    sidx[q][c] = indices[b*L + c];
    smk [q][c] = mask   [b*L + c];
    __syncthreads();
    float mv = warpsum(smk[q][c]);
    if ((t & 31) == 0) redm[q][(t >> 5) & 3] = mv;
    __syncthreads();
    float msum = redm[q][0]+redm[q][1]+redm[q][2]+redm[q][3];
    float2 acc = make_float2(0.f, 0.f);
    const float* ebase = embed + 2*c;
    #pragma unroll 8
    for (int l = 0; l < L; ++l) {
        float2 e = *(const float2*)(ebase + (size_t)sidx[q][l]*EDIM);
        float mk = smk[q][l];
        acc.x += e.x*mk; acc.y += e.y*mk;
    }
    float inv = 1.f / fmaxf(msum, 1.0f);
    *(float2*)(d_x + b*EDIM + 2*c) = make_float2(acc.x*inv, acc.y*inv);
}

// ---------------------------------------------------------------- featurize 32 rows (v[] preloaded)
struct FeatSm {
    float xs[EDIM*36];
    float spart [32][8];
    float sscale[32][4];
    int   sj[32];
};

__device__ __forceinline__ void featurize(FeatSm& s, float v[32], int rowbase, int t) {
    int lane = t & 31, warp = t >> 5;
    #pragma unroll
    for (int g = 0; g < 32; ++g) {
        s.xs[t*36 + g] = v[g];
        float ss = warpsum(v[g]*v[g]);
        if (lane == 0) s.spart[g][warp] = ss;
    }
    __syncthreads();

    if (t < 128) {     // combined full-row + per-head scale, one reduction round
        int g = t >> 2, h = t & 3;
        float tot = s.spart[g][0]+s.spart[g][1]+s.spart[g][2]+s.spart[g][3]
                  + s.spart[g][4]+s.spart[g][5]+s.spart[g][6]+s.spart[g][7];
        float hn  = s.spart[g][2*h] + s.spart[g][2*h+1];
        float S1  = fmaxf(sqrtf(tot), 1e-4f);
        float S2  = fmaxf(sqrtf(hn)/S1, 1e-4f);
        s.sscale[g][h] = 1.0f / (S1*S2);
    }
    __syncthreads();

    // ---- prf: thread t -> feat col t = (r,h,m); omega in registers ----
    {
        float om[64];
        const float* omp = d_omT + t;
        #pragma unroll
        for (int d = 0; d < 64; ++d) om[d] = omp[d*256];
        int h = (t >> 5) & 3, r = t >> 7;
        const float* xsh = s.xs + h*64*36;
        float qs = c_s[r];
        float sc = sqrtf(2.f*qs);
        float ml = sqrtf(c_w[r]) * INV_SQRT_M;
        float* outp = d_prf + (size_t)rowbase*256 + t;
        #pragma unroll
        for (int tile = 0; tile < 4; ++tile) {
            unsigned long long a0=0, a1=0, a2=0, a3=0;
            #pragma unroll
            for (int d = 0; d < 64; ++d) {
                unsigned long long o2; PACK2(o2, om[d]);
                const ulonglong2* xp = (const ulonglong2*)(xsh + d*36 + tile*8);
                ulonglong2 xa = xp[0], xb = xp[1];
                FFMA2(a0, xa.x, o2); FFMA2(a1, xa.y, o2);
                FFMA2(a2, xb.x, o2); FFMA2(a3, xb.y, o2);
            }
            unsigned long long aa[4] = {a0, a1, a2, a3};
            #pragma unroll
            for (int pr = 0; pr < 4; ++pr) {
                unsigned lo, hi; UNPACK2(lo, hi, aa[pr]);
                int g0 = tile*8 + pr*2;
                float f0 = __uint_as_float(lo) * s.sscale[g0  ][h];
                float f1 = __uint_as_float(hi) * s.sscale[g0+1][h];
                outp[(size_t)(g0  )*256] = __expf(fminf(fmaxf(f0*sc - qs, -20.f), 20.f)) * ml;
                outp[(size_t)(g0+1)*256] = __expf(fminf(fmaxf(f1*sc - qs, -20.f), 20.f)) * ml;
            }
        }
    }

    // ---- poly: thread t -> (p, hh) x 8 rows; anchors in registers ----
    {
        int p = t & 15, hh = (t >> 4) & 3, slot = t >> 6;
        float an[64];
        #pragma unroll
        for (int d = 0; d < 64; ++d) an[d] = d_anchT[d*P + p];
        const float* xph = s.xs + hh*64*36 + slot*8;
        unsigned long long a0=0, a1=0, a2=0, a3=0;
        #pragma unroll
        for (int d = 0; d < 64; ++d) {
            unsigned long long o2; PACK2(o2, an[d]);
            const ulonglong2* xp = (const ulonglong2*)(xph + d*36);
            ulonglong2 xa = xp[0], xb = xp[1];
            FFMA2(a0, xa.x, o2); FFMA2(a1, xa.y, o2);
            FFMA2(a2, xb.x, o2); FFMA2(a3, xb.y, o2);
        }
        unsigned long long aa[4] = {a0, a1, a2, a3};
        #pragma unroll
        for (int pr = 0; pr < 4; ++pr) {
            unsigned lo, hi; UNPACK2(lo, hi, aa[pr]);
            int g0 = slot*8 + pr*2;
            float f0 = __uint_as_float(lo) * s.sscale[g0  ][hh];
            float f1 = __uint_as_float(hi) * s.sscale[g0+1][hh];
            f0 = fminf(fmaxf(f0, -1.f), 1.f);
            f1 = fminf(fmaxf(f1, -1.f), 1.f);
            d_poly[(size_t)(rowbase + g0  )*64 + hh*16 + p] = f0*f0*0.25f;
            d_poly[(size_t)(rowbase + g0+1)*64 + hh*16 + p] = f1*f1*0.25f;
        }
    }
}

// ---------------------------------------------------------------- featW: gather + featurize (stream 2)
__global__ void __launch_bounds__(256, 2) featW_kernel(
        const int* __restrict__ labels, const int* __restrict__ negidx,
        const float* __restrict__ kernelM) {
    __shared__ FeatSm sm;
    int t = threadIdx.x;
    int base = ROW_W0 + blockIdx.x * 32;
    if (t < 32) {
        int i = base + t - B;
        sm.sj[t] = (i < B*KPOS) ? max(__ldg(labels + i), 0) : __ldg(negidx + i - B*KPOS);
    }
    __syncthreads();
    float v[32];
    #pragma unroll
    for (int g = 0; g < 32; ++g) v[g] = __ldg(kernelM + (size_t)t*NUML + sm.sj[g]);
    featurize(sm, v, base, t);
}

// ---------------------------------------------------------------- featQ (stream 0, after pool)
__global__ void __launch_bounds__(256, 2) featQ_kernel() {
    __shared__ FeatSm sm;
    int t = threadIdx.x;
    int base = blockIdx.x * 32;
    float v[32];
    #pragma unroll
    for (int g = 0; g < 32; ++g) v[g] = d_x[(base + g)*EDIM + t];
    featurize(sm, v, base, t);
}

// ---------------------------------------------------------------- T = sum over neg rows of polyW (x) prfW
// 256 blocks (32 chunks x 8 rh), 2 iterations of 32 rows each.
__global__ void t_kernel() {
    int rh = blockIdx.x & 7, chunk = blockIdx.x >> 3;   // 32 chunks x 8 rh
    int r = rh >> 2, h = rh & 3;
    int t = threadIdx.x;                 // 512 threads
    int p = t >> 5, m = t & 31;
    __shared__ float spw[32][16];
    __shared__ float spf[32][32];
    float acc = 0.f;
    #pragma unroll
    for (int iter = 0; iter < 2; ++iter) {
        int bs = ROW_N0 + chunk*64 + iter*32;
        int lr = t >> 4, lp = t & 15;
        spw[lr][lp] = d_poly[(size_t)(bs + lr)*64 + h*16 + lp];
        int fr = t >> 5, fm = t & 31;
        spf[fr     ][fm] = d_prf[(size_t)(bs+fr   )*256 + r*128 + h*32 + fm];
        spf[fr + 16][fm] = d_prf[(size_t)(bs+fr+16)*256 + r*128 + h*32 + fm];
        __syncthreads();
        #pragma unroll
        for (int k = 0; k < 32; ++k) acc += spw[k][p]*spf[k][m];
        __syncthreads();
    }
    atomicAdd(&d_T[rh*512 + t], acc);
}

// ---------------------------------------------------------------- per-row loss (2 b per block) + final
__global__ void rowloss_kernel(const float* __restrict__ label_mask,
                               float* __restrict__ out) {
    __shared__ float spos[2][8];
    __shared__ float red [2][8];
    int t = threadIdx.x, lane = t & 31, warp = t >> 5;
    int b0 = blockIdx.x*2;

    // --- positive scores: warp handles b = b0+(warp>>2), k = (warp&3)*2 + {0,1} ---
    {
        int b = b0 + (warp >> 2);
        float2 pq = *(const float2*)(d_poly + (size_t)b*64 + lane*2);
        float score[2];
        #pragma unroll
        for (int kk = 0; kk < 2; ++kk) {
            int k = (warp & 3)*2 + kk;
            size_t g = (size_t)(ROW_W0 + b*KPOS + k);
            float2 pw = *(const float2*)(d_poly + g*64 + lane*2);
            float prod = pq.x*pw.x + pq.y*pw.y;       // partial polydot for h = lane>>3
            #pragma unroll
            for (int o = 4; o; o >>= 1) prod += __shfl_xor_sync(0xffffffffu, prod, o);
            float pdh[4];
            pdh[0] = __shfl_sync(0xffffffffu, prod, 0);
            pdh[1] = __shfl_sync(0xffffffffu, prod, 8);
            pdh[2] = __shfl_sync(0xffffffffu, prod, 16);
            pdh[3] = __shfl_sync(0xffffffffu, prod, 24);
            float val = 0.f;
            #pragma unroll
            for (int r = 0; r < R; ++r)
                #pragma unroll
                for (int h = 0; h < H; ++h)
                    val += pdh[h] * d_prf[(size_t)b*256 + r*128 + h*32 + lane]
                                  * d_prf[g*256 + r*128 + h*32 + lane];
            score[kk] = warpsum(val);
        }
        if (lane == 0) {
            spos[warp >> 2][(warp & 3)*2    ] = score[0];
            spos[warp >> 2][(warp & 3)*2 + 1] = score[1];
        }
    }

    // --- negative row-sums via T for both b's: thread t -> (r,h,m) ---
    {
        int r = t >> 7, h = (t >> 5) & 3, m = t & 31;
        const float* Tp = d_T + (r*4 + h)*512 + m;
        #pragma unroll
        for (int bb = 0; bb < 2; ++bb) {
            int b = b0 + bb;
            float a = 0.f;
            #pragma unroll
            for (int p = 0; p < P; ++p) a += d_poly[(size_t)b*64 + h*16 + p] * Tp[p*32];
            float nval = warpsum(d_prf[(size_t)b*256 + t] * a);
            if (lane == 0) red[bb][warp] = nval;
        }
    }
    __syncthreads();

    // --- epilogue: warp0 lane0 -> b0, warp1 lane0 -> b0+1 ---
    if (lane == 0 && warp < 2) {
        int bb = warp, b = b0 + bb;
        float S = (float)NNEG * 1e-8f;
        #pragma unroll
        for (int w = 0; w < 8; ++w) S += red[bb][w];
        #pragma unroll
        for (int k = 0; k < KPOS; ++k) S += spos[bb][k] + 1e-8f;
        float logS = logf(S);
        float lg = 0.f, lm = 0.f;
        #pragma unroll
        for (int k = 0; k < KPOS; ++k) {
            float mk = label_mask[b*KPOS + k];
            lg += mk * (logf(spos[bb][k] + 1e-8f) - logS);
            lm += mk;
        }
        atomicAdd(&d_acc[0], lg);
        atomicAdd(&d_acc[1], lm);
        __threadfence();
        if (atomicAdd(&d_cnt, 1u) == (unsigned)(B - 1)) {
            __threadfence();
            out[0] = -d_acc[0] / (d_acc[1] + 1e-6f);
        }
    }
}

// ---------------------------------------------------------------- launch (round-8 fork-join shape)
static cudaStream_t g_s2 = 0;
static cudaEvent_t  g_ev0 = 0, g_ev2 = 0;

extern "C" void kernel_launch(void* const* d_in, const int* in_sizes, int n_in,
                              void* d_out, int out_size) {
    const int*   indices    = (const int*)  d_in[0];
    const float* mask       = (const float*)d_in[1];
    const int*   labels     = (const int*)  d_in[2];
    const float* label_mask = (const float*)d_in[3];
    const int*   neg_idx    = (const int*)  d_in[4];
    const float* embed      = (const float*)d_in[5];
    const float* kernelM    = (const float*)d_in[6];
    const float* omega      = (const float*)d_in[7];
    const float* anchors    = (const float*)d_in[8];
    float* out = (float*)d_out;

    if (!g_s2) {   // host-side objects only; identical device work every call
        cudaStreamCreateWithFlags(&g_s2, cudaStreamNonBlocking);
        cudaEventCreateWithFlags(&g_ev0, cudaEventDisableTiming);
        cudaEventCreateWithFlags(&g_ev2, cudaEventDisableTiming);
    }

    // stream 0: prep first (capture stream), then fork
    prep_kernel<<<69, 256>>>(anchors, omega);
    cudaEventRecord(g_ev0, 0);
    cudaStreamWaitEvent(g_s2, g_ev0, 0);

    // stream 2: W-feature pipeline
    featW_kernel<<<NW/32, 256, 0, g_s2>>>(labels, neg_idx, kernelM);
    t_kernel    <<<256,   512, 0, g_s2>>>();
    cudaEventRecord(g_ev2, g_s2);

    // stream 0: query pipeline
    pool_kernel <<<B/2, 256>>>(indices, mask, embed);
    featQ_kernel<<<B/32, 256>>>();

    cudaStreamWaitEvent(0, g_ev2, 0);
    rowloss_kernel<<<B/2, 256>>>(label_mask, out);
}